// round 9
// baseline (speedup 1.0000x reference)
#include <cuda_runtime.h>
#include <math.h>

#define NB 64
#define NC 64
#define NT 512
#define NV 25
#define NK 3
#define NO 64

// -------- scratch (device globals) --------
__device__ float g_Y[(size_t)NB * NO * NT * NV];   // GCN output after BN+hswish

__device__ __forceinline__ float hswish(float x) {
    return x * fminf(fmaxf(x + 3.0f, 0.0f), 6.0f) * (1.0f / 6.0f);
}

// ===================== K1: GCN (An fold + einsum + BN + hswish) =====================
// grid (T/TT, B), 256 threads. Body identical to the proven R2 kernel; the only
// addition is the in-kernel dsh/An computation (replaces the old prep kernel).
// smem floats:
//   Xs  [64][100]   @0      6400
//   Us  [192][100]  @6400   19200
//   Ws  [192][64]   @25600  12288
//   An  [75][32]    @37888  2400
//   dsh [80]        @40288  80
#define TT 4
#define P1 (TT * NV)  /* 100 */
#define GC_US 6400
#define GC_WS 25600
#define GC_AN 37888
#define GC_DSH 40288
#define GC_TOT 40368

__global__ void __launch_bounds__(256, 1)
gcn_kernel(const float* __restrict__ x,
           const float* __restrict__ Af, const float* __restrict__ Al,
           const float* __restrict__ Wg,
           const float* __restrict__ gscale, const float* __restrict__ gbias) {
    extern __shared__ float sm[];
    float* Xs = sm;
    float* Us = sm + GC_US;
    float* Ws = sm + GC_WS;
    float* An = sm + GC_AN;
    float* dsh = sm + GC_DSH;

    int tid = threadIdx.x;
    int t0 = blockIdx.x * TT;
    int b = blockIdx.y;

    // ---- cooperative loads ----
    {
        const float4* xsrc = (const float4*)(x + ((size_t)b * NC * NT + t0) * NV);
        for (int i = tid; i < 1600; i += 256) {
            int c = i / 25, q = i - c * 25;
            ((float4*)Xs)[i] = xsrc[c * 3200 + q];   // c stride = T*V/4 = 3200 float4
        }
        const float4* wsrc = (const float4*)Wg;
        for (int i = tid; i < 3072; i += 256) ((float4*)Ws)[i] = wsrc[i];
    }
    // ---- D^{-1/2} row factors ----
    if (tid < NK * NV) {
        const float* af = Af + tid * NV;
        const float* al = Al + tid * NV;
        float s = 0.0f;
        #pragma unroll
        for (int w = 0; w < NV; w++) s += fabsf(af[w] + al[w]);
        dsh[tid] = rsqrtf(fmaxf(s, 1e-6f));
    }
    __syncthreads();
    // ---- An fill: An[k*25+v][w] = dsh[k,v] * |Af+Al| * dsh[k,w], pad w>=25 with 0 ----
    for (int i = tid; i < NK * NV * 32; i += 256) {
        int row = i >> 5;          // k*25+v
        int w = i & 31;
        float val = 0.0f;
        if (w < NV) {
            int k = row / NV;
            int src = row * NV + w;
            val = dsh[row] * fabsf(Af[src] + Al[src]) * dsh[k * NV + w];
        }
        An[i] = val;
    }
    __syncthreads();

    // ---- stage A: Us[j][p] = sum_c Ws[j][c] * Xs[c][p],  j = k*64+o (192 rows) ----
    {
        int jg = tid >> 5;   // 0..7
        int pt = tid & 31;
        bool v3 = (pt < P1 - 96);  // p = pt+96 valid only for pt<4
        for (int jo = 0; jo < 3; jo++) {
            int jb = jo * 64 + jg * 8;
            float acc[8][4];
            #pragma unroll
            for (int u = 0; u < 8; u++)
                #pragma unroll
                for (int i = 0; i < 4; i++) acc[u][i] = 0.0f;
            for (int c = 0; c < NC; c++) {
                float xv0 = Xs[c * P1 + pt];
                float xv1 = Xs[c * P1 + pt + 32];
                float xv2 = Xs[c * P1 + pt + 64];
                float xv3 = v3 ? Xs[c * P1 + pt + 96] : 0.0f;
                #pragma unroll
                for (int u = 0; u < 8; u++) {
                    float wv = Ws[(jb + u) * 64 + c];
                    acc[u][0] = fmaf(wv, xv0, acc[u][0]);
                    acc[u][1] = fmaf(wv, xv1, acc[u][1]);
                    acc[u][2] = fmaf(wv, xv2, acc[u][2]);
                    acc[u][3] = fmaf(wv, xv3, acc[u][3]);
                }
            }
            #pragma unroll
            for (int u = 0; u < 8; u++) {
                Us[(jb + u) * P1 + pt]      = acc[u][0];
                Us[(jb + u) * P1 + pt + 32] = acc[u][1];
                Us[(jb + u) * P1 + pt + 64] = acc[u][2];
                if (v3) Us[(jb + u) * P1 + pt + 96] = acc[u][3];
            }
        }
    }
    __syncthreads();

    // ---- stage B: y[o][tt][w] = sum_{k,v} Us[(k*64+o)][tt*25+v] * An[k][v][w] ----
    {
        int o = tid >> 2;
        int tt = tid & 3;
        float acc[28];
        #pragma unroll
        for (int w = 0; w < 28; w++) acc[w] = 0.0f;
        #pragma unroll
        for (int k = 0; k < NK; k++) {
            const float* Uko = Us + (k * 64 + o) * P1 + tt * NV;
            const float4* A4 = (const float4*)(An + k * NV * 32);
            #pragma unroll 5
            for (int v = 0; v < NV; v++) {
                float uv = Uko[v];
                const float4* row = A4 + v * 8;
                #pragma unroll
                for (int q = 0; q < 7; q++) {
                    float4 av = row[q];
                    acc[q * 4 + 0] = fmaf(uv, av.x, acc[q * 4 + 0]);
                    acc[q * 4 + 1] = fmaf(uv, av.y, acc[q * 4 + 1]);
                    acc[q * 4 + 2] = fmaf(uv, av.z, acc[q * 4 + 2]);
                    acc[q * 4 + 3] = fmaf(uv, av.w, acc[q * 4 + 3]);
                }
            }
        }
        float s = gscale[o] * (1.0f / 3.0f);   // fold the 1/K average
        float bi = gbias[o];
        float* yo = g_Y + (((size_t)b * NO + o) * NT + t0 + tt) * NV;
        #pragma unroll
        for (int w = 0; w < NV; w++) {
            float vv = acc[w] * s + bi;
            yo[w] = hswish(vv);
        }
    }
}

// ===================== K2: TCN =====================
// grid (T/TT2, B), 256 threads, 2 blocks/SM. Same as the proven R2 kernel except
// the depthwise stage reads g_Y through L1 (no Ys smem staging): smem 174->72 KB.
// smem floats:
//   T1  [64][200]  @0      12800
//   Pw  [64][64]   @12800  4096   (transposed: [c][o])
//   Dw  [64][12]   @16896  768
//   PR  [256]      @17664  256    (S1|B1|S2|B2)
#define TT2 8
#define P2 (TT2 * NV)   /* 200 */
#define TC_PW 12800
#define TC_DW 16896
#define TC_PR 17664
#define TC_TOT 17920

__global__ void __launch_bounds__(256, 2)
tcn_kernel(const float* __restrict__ x,
           const float* __restrict__ dwg, const float* __restrict__ pwg,
           const float* __restrict__ s1g, const float* __restrict__ b1g,
           const float* __restrict__ s2g, const float* __restrict__ b2g,
           float* __restrict__ out) {
    extern __shared__ float sm[];
    float* T1 = sm;
    float* Pw = sm + TC_PW;
    float* Dw = sm + TC_DW;
    float* PR = sm + TC_PR;

    int tid = threadIdx.x;
    int t0 = blockIdx.x * TT2;
    int b = blockIdx.y;

    // ---- param loads ----
    for (int i = tid; i < NO * NC; i += 256) {
        int o = i / 64, c = i - o * 64;
        Pw[c * 64 + o] = pwg[i];   // transpose for broadcast reads
    }
    for (int i = tid; i < NO * 9; i += 256) {
        int c = i / 9, j = i - c * 9;
        Dw[c * 12 + j] = dwg[i];
    }
    if (tid < 64) {
        PR[tid] = s1g[tid]; PR[64 + tid] = b1g[tid];
        PR[128 + tid] = s2g[tid]; PR[192 + tid] = b2g[tid];
    }
    __syncthreads();

    // ---- depthwise k=9 + BN1 + hswish -> T1 (g_Y via L1) ----
    const float* Yb = g_Y + ((size_t)b * NO * NT + t0) * NV;
    bool interior = (t0 >= 4) && (t0 + TT2 + 4 <= NT);
    for (int i = tid; i < NC * P2; i += 256) {
        int c = i / P2, p = i - c * P2;
        int tt = p / NV, v = p - tt * NV;
        const float* yp = Yb + c * (NT * NV) + (tt - 4) * NV + v;   // tap j=0 -> t0+tt-4
        const float* dr = Dw + c * 12;
        float a = 0.0f;
        if (interior) {
            #pragma unroll
            for (int j = 0; j < 9; j++) a = fmaf(__ldg(yp + j * NV), dr[j], a);
        } else {
            int tg0 = t0 + tt - 4;
            #pragma unroll
            for (int j = 0; j < 9; j++) {
                int tg = tg0 + j;
                if (tg >= 0 && tg < NT) a = fmaf(__ldg(yp + j * NV), dr[j], a);
            }
        }
        T1[i] = hswish(a * PR[c] + PR[64 + c]);
    }
    __syncthreads();

    // ---- pointwise (64x64) + BN2 + residual + hswish ----
    int og = tid >> 5;   // owns o = og*8 .. og*8+7
    int pt = tid & 31;
    bool v6 = (pt < P2 - 192);   // p = pt+192 valid only for pt<8
    float acc[8][7];
    #pragma unroll
    for (int u = 0; u < 8; u++)
        #pragma unroll
        for (int i = 0; i < 7; i++) acc[u][i] = 0.0f;

    for (int c = 0; c < NC; c++) {
        float tv[7];
        #pragma unroll
        for (int i = 0; i < 6; i++) tv[i] = T1[c * P2 + pt + 32 * i];
        tv[6] = v6 ? T1[c * P2 + pt + 192] : 0.0f;
        const float* pr = Pw + c * 64 + og * 8;
        #pragma unroll
        for (int u = 0; u < 8; u++) {
            float wv = pr[u];
            #pragma unroll
            for (int i = 0; i < 7; i++) acc[u][i] = fmaf(wv, tv[i], acc[u][i]);
        }
    }

    #pragma unroll
    for (int u = 0; u < 8; u++) {
        int o = og * 8 + u;
        float sc = PR[128 + o], bb = PR[192 + o];
        const float* xr = x + (((size_t)b * NC + o) * NT + t0) * NV;
        float* orow = out + (((size_t)b * NO + o) * NT + t0) * NV;
        #pragma unroll
        for (int i = 0; i < 7; i++) {
            int p = pt + 32 * i;
            if (p < P2) {
                float vv = acc[u][i] * sc + bb + __ldg(&xr[p]);
                orow[p] = hswish(vv);
            }
        }
    }
}

// ===================== launcher =====================
extern "C" void kernel_launch(void* const* d_in, const int* in_sizes, int n_in,
                              void* d_out, int out_size) {
    const float* x  = (const float*)d_in[0];
    const float* Af = (const float*)d_in[1];
    const float* Al = (const float*)d_in[2];
    const float* Wg = (const float*)d_in[3];
    const float* gs = (const float*)d_in[4];
    const float* gb = (const float*)d_in[5];
    const float* dw = (const float*)d_in[6];
    const float* pw = (const float*)d_in[7];
    const float* s1 = (const float*)d_in[8];
    const float* b1 = (const float*)d_in[9];
    const float* s2 = (const float*)d_in[10];
    const float* b2 = (const float*)d_in[11];
    float* out = (float*)d_out;

    (void)in_sizes; (void)n_in; (void)out_size;

    cudaFuncSetAttribute(gcn_kernel, cudaFuncAttributeMaxDynamicSharedMemorySize,
                         GC_TOT * (int)sizeof(float));
    cudaFuncSetAttribute(tcn_kernel, cudaFuncAttributeMaxDynamicSharedMemorySize,
                         TC_TOT * (int)sizeof(float));

    gcn_kernel<<<dim3(NT / TT, NB), 256, GC_TOT * sizeof(float)>>>(x, Af, Al, Wg, gs, gb);
    tcn_kernel<<<dim3(NT / TT2, NB), 256, TC_TOT * sizeof(float)>>>(x, dw, pw, s1, b1, s2, b2, out);
}

// round 13
// speedup vs baseline: 1.0344x; 1.0344x over previous
#include <cuda_runtime.h>
#include <math.h>

#define NB 64
#define NC 64
#define NT 512
#define NV 25
#define NK 3
#define NO 64

// -------- scratch (device globals) --------
__device__ float g_Y[(size_t)NB * NO * NT * NV];   // GCN output after BN+hswish
__device__ float g_An[NK * NV * 32];               // A_norm, padded w-stride 32

__device__ __forceinline__ float hswish(float x) {
    return x * fminf(fmaxf(x + 3.0f, 0.0f), 6.0f) * (1.0f / 6.0f);
}

// ===================== K0: adjacency normalization =====================
__global__ void prep_kernel(const float* __restrict__ Af, const float* __restrict__ Al) {
    __shared__ float dsh[NK * NV];
    int tid = threadIdx.x;
    if (tid < NK * NV) {
        int base = tid * NV;
        float s = 0.0f;
        #pragma unroll
        for (int w = 0; w < NV; w++) s += fabsf(Af[base + w] + Al[base + w]);
        dsh[tid] = rsqrtf(fmaxf(s, 1e-6f));
    }
    __syncthreads();
    for (int i = tid; i < NK * NV * 32; i += blockDim.x) {
        int row = i >> 5;          // k*25+v
        int w = i & 31;
        float val = 0.0f;
        if (w < NV) {
            int k = row / NV;
            int src = row * NV + w;
            float a = fabsf(Af[src] + Al[src]);
            val = dsh[row] * a * dsh[k * NV + w];
        }
        g_An[i] = val;
    }
}

// ===================== K1: GCN (byte-identical to the proven R2 kernel) =====================
// grid (T/TT, B), 256 threads.
// smem floats: Xs[64][100] @0 6400, Us[192][100] @6400 19200,
//              Ws[192][64] @25600 12288, An[75][32] @37888 2400
#define TT 4
#define P1 (TT * NV)  /* 100 */
#define SM1_FLOATS (6400 + 19200 + 12288 + 2400)

__global__ void __launch_bounds__(256, 1)
gcn_kernel(const float* __restrict__ x, const float* __restrict__ Wg,
           const float* __restrict__ gscale, const float* __restrict__ gbias) {
    extern __shared__ float sm[];
    float* Xs = sm;
    float* Us = sm + 6400;
    float* Ws = sm + 25600;
    float* An = sm + 37888;

    int tid = threadIdx.x;
    int t0 = blockIdx.x * TT;
    int b = blockIdx.y;

    // ---- cooperative loads ----
    const float* xb = x + (size_t)b * NC * NT * NV + (size_t)t0 * NV;
    for (int i = tid; i < NC * P1; i += 256) {
        int c = i / P1, q = i - c * P1;
        Xs[i] = xb[(size_t)c * NT * NV + q];
    }
    for (int i = tid; i < NK * NO * NC; i += 256) Ws[i] = Wg[i];
    for (int i = tid; i < NK * NV * 32; i += 256) An[i] = g_An[i];
    __syncthreads();

    // ---- stage A: Us[j][p] = sum_c Ws[j][c] * Xs[c][p] ----
    {
        int jg = tid >> 5;   // 0..7
        int pt = tid & 31;
        bool v3 = (pt < P1 - 96);
        for (int jo = 0; jo < 3; jo++) {
            int jb = jo * 64 + jg * 8;
            float acc[8][4];
            #pragma unroll
            for (int u = 0; u < 8; u++)
                #pragma unroll
                for (int i = 0; i < 4; i++) acc[u][i] = 0.0f;
            for (int c = 0; c < NC; c++) {
                float xv0 = Xs[c * P1 + pt];
                float xv1 = Xs[c * P1 + pt + 32];
                float xv2 = Xs[c * P1 + pt + 64];
                float xv3 = v3 ? Xs[c * P1 + pt + 96] : 0.0f;
                #pragma unroll
                for (int u = 0; u < 8; u++) {
                    float wv = Ws[(jb + u) * 64 + c];
                    acc[u][0] = fmaf(wv, xv0, acc[u][0]);
                    acc[u][1] = fmaf(wv, xv1, acc[u][1]);
                    acc[u][2] = fmaf(wv, xv2, acc[u][2]);
                    acc[u][3] = fmaf(wv, xv3, acc[u][3]);
                }
            }
            #pragma unroll
            for (int u = 0; u < 8; u++) {
                Us[(jb + u) * P1 + pt]      = acc[u][0];
                Us[(jb + u) * P1 + pt + 32] = acc[u][1];
                Us[(jb + u) * P1 + pt + 64] = acc[u][2];
                if (v3) Us[(jb + u) * P1 + pt + 96] = acc[u][3];
            }
        }
    }
    __syncthreads();

    // ---- stage B ----
    {
        int o = tid >> 2;
        int tt = tid & 3;
        float acc[28];
        #pragma unroll
        for (int w = 0; w < 28; w++) acc[w] = 0.0f;
        #pragma unroll
        for (int k = 0; k < NK; k++) {
            const float* Uko = Us + (k * 64 + o) * P1 + tt * NV;
            const float4* A4 = (const float4*)(An + k * NV * 32);
            #pragma unroll 5
            for (int v = 0; v < NV; v++) {
                float uv = Uko[v];
                const float4* row = A4 + v * 8;
                #pragma unroll
                for (int q = 0; q < 7; q++) {
                    float4 av = row[q];
                    acc[q * 4 + 0] = fmaf(uv, av.x, acc[q * 4 + 0]);
                    acc[q * 4 + 1] = fmaf(uv, av.y, acc[q * 4 + 1]);
                    acc[q * 4 + 2] = fmaf(uv, av.z, acc[q * 4 + 2]);
                    acc[q * 4 + 3] = fmaf(uv, av.w, acc[q * 4 + 3]);
                }
            }
        }
        float s = __ldg(&gscale[o]) * (1.0f / 3.0f);
        float bi = __ldg(&gbias[o]);
        float* yo = g_Y + (((size_t)b * NO + o) * NT + t0 + tt) * NV;
        #pragma unroll
        for (int w = 0; w < NV; w++) {
            float vv = acc[w] * s + bi;
            yo[w] = hswish(vv);
        }
    }
}

// ===================== K2: TCN =====================
// R2 structure, but Ys staged in 4 channel-chunks of 16 -> smem 174 KB -> 97.3 KB
// -> 2 blocks/SM. Depthwise + pointwise math identical to R2.
// smem floats: Ysq[16][16][25] @0 6400, T1[64][200] @6400 12800,
//              Pw[64][64] @19200 4096, Dw[64][12] @23296 768, PR[256] @24064
#define TT2 8
#define HT (TT2 + 8)    /* 16 */
#define P2 (TT2 * NV)   /* 200 */
#define TC_T1 6400
#define TC_PW 19200
#define TC_DW 23296
#define TC_PR 24064
#define SM2_FLOATS 24320

__global__ void __launch_bounds__(256, 2)
tcn_kernel(const float* __restrict__ x,
           const float* __restrict__ dwg, const float* __restrict__ pwg,
           const float* __restrict__ s1g, const float* __restrict__ b1g,
           const float* __restrict__ s2g, const float* __restrict__ b2g,
           float* __restrict__ out) {
    extern __shared__ float sm[];
    float* Ysq = sm;
    float* T1 = sm + TC_T1;
    float* Pw = sm + TC_PW;
    float* Dw = sm + TC_DW;
    float* PR = sm + TC_PR;

    int tid = threadIdx.x;
    int t0 = blockIdx.x * TT2;
    int b = blockIdx.y;

    // ---- param loads ----
    for (int i = tid; i < NO * NC; i += 256) {
        int o = i / 64, c = i - o * 64;
        Pw[c * 64 + o] = pwg[i];   // transposed for broadcast reads
    }
    for (int i = tid; i < NO * 9; i += 256) {
        int c = i / 9, j = i - c * 9;
        Dw[c * 12 + j] = dwg[i];
    }
    if (tid < 64) {
        PR[tid] = s1g[tid]; PR[64 + tid] = b1g[tid];
        PR[128 + tid] = s2g[tid]; PR[192 + tid] = b2g[tid];
    }
    __syncthreads();

    bool interior = (blockIdx.x > 0) && (blockIdx.x < (int)gridDim.x - 1);

    // ---- depthwise k=9 + BN1 + hswish -> T1, in 4 channel chunks of 16 ----
    for (int cq = 0; cq < 4; cq++) {
        int cbase = cq * 16;
        // load Ysq for channels cbase..cbase+15, t rows t0-4..t0+11
        if (interior) {
            const float4* ysrc = (const float4*)(g_Y +
                ((size_t)b * NO * NT + (t0 - 4)) * NV);
            for (int i = tid; i < 1600; i += 256) {      // 16 ch * 100 float4
                int cl = i / 100, q = i - cl * 100;
                ((float4*)Ysq)[i] = ysrc[(size_t)(cbase + cl) * 3200 + q];
            }
        } else {
            for (int i = tid; i < 16 * HT * NV; i += 256) {
                int cl = i / (HT * NV);
                int q = i - cl * (HT * NV);
                int tt = q / NV, v = q - tt * NV;
                int tg = t0 - 4 + tt;
                float val = 0.0f;
                if (tg >= 0 && tg < NT)
                    val = g_Y[(((size_t)b * NO + cbase + cl) * NT + tg) * NV + v];
                Ysq[i] = val;
            }
        }
        __syncthreads();

        // compute T1 rows for these 16 channels: 16*200 = 3200 items
        for (int i = tid; i < 3200; i += 256) {
            int cl = i / P2, p = i - cl * P2;
            int tt = p / NV, v = p - tt * NV;
            int c = cbase + cl;
            const float* yr = Ysq + cl * (HT * NV) + tt * NV + v;
            const float* dr = Dw + c * 12;
            float acc = 0.0f;
            #pragma unroll
            for (int j = 0; j < 9; j++) acc = fmaf(yr[j * NV], dr[j], acc);
            float vv = acc * PR[c] + PR[64 + c];
            T1[c * P2 + p] = hswish(vv);
        }
        __syncthreads();
    }

    // ---- pointwise (64x64) + BN2 + residual + hswish (identical to R2) ----
    int og = tid >> 5;
    int pt = tid & 31;
    bool v6 = (pt < P2 - 192);
    float acc[8][7];
    #pragma unroll
    for (int u = 0; u < 8; u++)
        #pragma unroll
        for (int i = 0; i < 7; i++) acc[u][i] = 0.0f;

    for (int c = 0; c < NC; c++) {
        float tv[7];
        #pragma unroll
        for (int i = 0; i < 6; i++) tv[i] = T1[c * P2 + pt + 32 * i];
        tv[6] = v6 ? T1[c * P2 + pt + 192] : 0.0f;
        const float* pr = Pw + c * 64 + og * 8;
        #pragma unroll
        for (int u = 0; u < 8; u++) {
            float wv = pr[u];
            #pragma unroll
            for (int i = 0; i < 7; i++) acc[u][i] = fmaf(wv, tv[i], acc[u][i]);
        }
    }

    #pragma unroll
    for (int u = 0; u < 8; u++) {
        int o = og * 8 + u;
        float sc = PR[128 + o], bb = PR[192 + o];
        const float* xr = x + (((size_t)b * NC + o) * NT + t0) * NV;
        float* orow = out + (((size_t)b * NO + o) * NT + t0) * NV;
        #pragma unroll
        for (int i = 0; i < 7; i++) {
            int p = pt + 32 * i;
            if (p < P2) {
                float vv = acc[u][i] * sc + bb + __ldg(&xr[p]);
                orow[p] = hswish(vv);
            }
        }
    }
}

// ===================== launcher =====================
extern "C" void kernel_launch(void* const* d_in, const int* in_sizes, int n_in,
                              void* d_out, int out_size) {
    const float* x  = (const float*)d_in[0];
    const float* Af = (const float*)d_in[1];
    const float* Al = (const float*)d_in[2];
    const float* Wg = (const float*)d_in[3];
    const float* gs = (const float*)d_in[4];
    const float* gb = (const float*)d_in[5];
    const float* dw = (const float*)d_in[6];
    const float* pw = (const float*)d_in[7];
    const float* s1 = (const float*)d_in[8];
    const float* b1 = (const float*)d_in[9];
    const float* s2 = (const float*)d_in[10];
    const float* b2 = (const float*)d_in[11];
    float* out = (float*)d_out;

    (void)in_sizes; (void)n_in; (void)out_size;

    cudaFuncSetAttribute(gcn_kernel, cudaFuncAttributeMaxDynamicSharedMemorySize,
                         SM1_FLOATS * (int)sizeof(float));
    cudaFuncSetAttribute(tcn_kernel, cudaFuncAttributeMaxDynamicSharedMemorySize,
                         SM2_FLOATS * (int)sizeof(float));

    prep_kernel<<<1, 128>>>(Af, Al);
    gcn_kernel<<<dim3(NT / TT, NB), 256, SM1_FLOATS * sizeof(float)>>>(x, Wg, gs, gb);
    tcn_kernel<<<dim3(NT / TT2, NB), 256, SM2_FLOATS * sizeof(float)>>>(x, dw, pw, s1, b1, s2, b2, out);
}

// round 14
// speedup vs baseline: 1.4817x; 1.4324x over previous
#include <cuda_runtime.h>
#include <math.h>

typedef unsigned long long u64;

#define NB 64
#define NC 64
#define NT 512
#define NV 25
#define NK 3
#define NO 64

// -------- scratch (device globals) --------
__device__ float g_Y[(size_t)NB * NO * NT * NV];   // GCN output after BN+hswish

__device__ __forceinline__ float hswish(float x) {
    return x * fminf(fmaxf(x + 3.0f, 0.0f), 6.0f) * (1.0f / 6.0f);
}
__device__ __forceinline__ u64 ffma2(u64 a, u64 b, u64 c) {
    u64 d; asm("fma.rn.f32x2 %0, %1, %2, %3;" : "=l"(d) : "l"(a), "l"(b), "l"(c)); return d;
}
__device__ __forceinline__ u64 dup2(float v) {
    u64 d; asm("mov.b64 %0, {%1, %1};" : "=l"(d) : "f"(v)); return d;
}
__device__ __forceinline__ void unpk(u64 p, float& lo, float& hi) {
    asm("mov.b64 {%0, %1}, %2;" : "=f"(lo), "=f"(hi) : "l"(p));
}

// ===================== K1: GCN (== 1335us champion + in-kernel An fold) =====================
// grid (T/TT, B), 256 thr, 2 blocks/SM. k loop outermost: Uk[64][100] per k,
// stage-B accumulators persist in registers across k.
// smem floats: Xs[64*100]=6400 @0, Uk[64*100]=6400 @6400, Ws[192*64]=12288 @12800,
//              An[75*32]=2400 @25088, dsh[80] @27488 -> 27568 fl = 110,272 B
#define TT 4
#define P1 100
#define GC_UK 6400
#define GC_WS 12800
#define GC_AN 25088
#define GC_DSH 27488
#define GC_TOT 27568

__global__ void __launch_bounds__(256, 2)
gcn_kernel(const float* __restrict__ x,
           const float* __restrict__ Af, const float* __restrict__ Al,
           const float* __restrict__ Wg,
           const float* __restrict__ gscale, const float* __restrict__ gbias) {
    extern __shared__ float sm[];
    float* Xs = sm;
    float* Uk = sm + GC_UK;
    float* Ws = sm + GC_WS;
    float* An = sm + GC_AN;
    float* dsh = sm + GC_DSH;

    int tid = threadIdx.x;
    int t0 = blockIdx.x * TT;
    int b = blockIdx.y;

    // ---- D^{-1/2} row factors (replaces the old prep kernel) ----
    if (tid < NK * NV) {
        const float* af = Af + tid * NV;
        const float* al = Al + tid * NV;
        float s = 0.0f;
        #pragma unroll
        for (int w = 0; w < NV; w++) s += fabsf(af[w] + al[w]);
        dsh[tid] = rsqrtf(fmaxf(s, 1e-6f));
    }
    // ---- cooperative loads (all float4) ----
    {
        const float4* xsrc = (const float4*)(x + ((size_t)b * NC * NT + t0) * NV);
        for (int i = tid; i < 1600; i += 256) {
            int c = i / 25, q = i - c * 25;
            ((float4*)Xs)[i] = xsrc[c * 3200 + q];   // c stride = T*V/4 = 3200 float4
        }
        const float4* wsrc = (const float4*)Wg;
        for (int i = tid; i < 3072; i += 256) ((float4*)Ws)[i] = wsrc[i];
    }
    __syncthreads();
    // ---- An fill: An[k*25+v][w] = dsh[k,v]*|Af+Al|*dsh[k,w]; pad w>=25 = 0 ----
    for (int i = tid; i < NK * NV * 32; i += 256) {
        int row = i >> 5;          // k*25+v
        int w = i & 31;
        float val = 0.0f;
        if (w < NV) {
            int k = row / NV;
            int src = row * NV + w;
            val = dsh[row] * fabsf(Af[src] + Al[src]) * dsh[k * NV + w];
        }
        An[i] = val;
    }
    __syncthreads();

    int jg = tid >> 5, pt = tid & 31;
    bool hiok = (pt < 18);          // second col-pair (64+2pt,65+2pt) < 100
    int o = tid >> 2, ttl = tid & 3;

    u64 bacc[14];
    #pragma unroll
    for (int j = 0; j < 14; j++) bacc[j] = 0ull;

    for (int k = 0; k < NK; k++) {
        // ---- stage A: Uk[o][p] = sum_c Ws[k*64+o][c] * Xs[c][p] ----
        u64 acc[8][2];
        #pragma unroll
        for (int r = 0; r < 8; r++) { acc[r][0] = 0ull; acc[r][1] = 0ull; }
        const float* Wr = Ws + (k * 64 + jg * 8) * 64;
        for (int c4 = 0; c4 < 16; c4++) {
            u64 xv0[4], xv1[4];
            #pragma unroll
            for (int cc = 0; cc < 4; cc++) {
                const float* xp = Xs + (c4 * 4 + cc) * P1;
                xv0[cc] = *(const u64*)(xp + 2 * pt);
                xv1[cc] = hiok ? *(const u64*)(xp + 64 + 2 * pt) : 0ull;
            }
            #pragma unroll
            for (int r = 0; r < 8; r++) {
                float4 w4 = *(const float4*)(Wr + r * 64 + c4 * 4);
                u64 w;
                w = dup2(w4.x); acc[r][0] = ffma2(w, xv0[0], acc[r][0]); acc[r][1] = ffma2(w, xv1[0], acc[r][1]);
                w = dup2(w4.y); acc[r][0] = ffma2(w, xv0[1], acc[r][0]); acc[r][1] = ffma2(w, xv1[1], acc[r][1]);
                w = dup2(w4.z); acc[r][0] = ffma2(w, xv0[2], acc[r][0]); acc[r][1] = ffma2(w, xv1[2], acc[r][1]);
                w = dup2(w4.w); acc[r][0] = ffma2(w, xv0[3], acc[r][0]); acc[r][1] = ffma2(w, xv1[3], acc[r][1]);
            }
        }
        #pragma unroll
        for (int r = 0; r < 8; r++) {
            float* up = Uk + (jg * 8 + r) * P1;
            *(u64*)(up + 2 * pt) = acc[r][0];
            if (hiok) *(u64*)(up + 64 + 2 * pt) = acc[r][1];
        }
        __syncthreads();

        // ---- stage B: bacc[o][tt][w-pairs] += Uk[o][tt*25+v] * An[k][v][w] ----
        {
            const float* Ur = Uk + o * P1 + ttl * NV;
            const float* Ar = An + k * (NV * 32);
            #pragma unroll 5
            for (int v = 0; v < NV; v++) {
                u64 uv = dup2(Ur[v]);
                const ulonglong2* A2 = (const ulonglong2*)(Ar + v * 32);
                #pragma unroll
                for (int q = 0; q < 7; q++) {
                    ulonglong2 aa = A2[q];
                    bacc[2 * q]     = ffma2(uv, aa.x, bacc[2 * q]);
                    bacc[2 * q + 1] = ffma2(uv, aa.y, bacc[2 * q + 1]);
                }
            }
        }
        __syncthreads();   // Uk reuse next k / staging reuse in epilogue
    }

    // ---- epilogue: BN + hswish -> stage to Xs -> coalesced float4 store ----
    {
        float s = gscale[o] * (1.0f / 3.0f);   // fold 1/K
        float bi = gbias[o];
        float* yrow = Xs + o * P1 + ttl * NV;
        #pragma unroll
        for (int j = 0; j < 13; j++) {
            float lo, hi; unpk(bacc[j], lo, hi);
            yrow[2 * j] = hswish(lo * s + bi);
            if (2 * j + 1 < NV) yrow[2 * j + 1] = hswish(hi * s + bi);
        }
    }
    __syncthreads();
    {
        float4* ydst = (float4*)(g_Y + ((size_t)b * NO * NT + t0) * NV);
        for (int i = tid; i < 1600; i += 256) {
            int oo = i / 25, q = i - oo * 25;
            ydst[oo * 3200 + q] = ((const float4*)Xs)[i];
        }
    }
}

// ===================== K2: TCN (== 1335us champion, verbatim) =====================
// grid (T/TT2, B), 256 thr, 2 blocks/SM. TT2=4, halo rows 12.
// smem floats: Ys[64*12*25]=19200 @0, T1[64*100]=6400 @19200,
//              Dw[64*12]=768 @25600, PR[256] @26368 -> 26624 fl = 106,496 B
#define TT2 4
#define HT2 12
#define P2 100
#define TC_T1 19200
#define TC_DW 25600
#define TC_PR 26368
#define TC_TOT 26624

__global__ void __launch_bounds__(256, 2)
tcn_kernel(const float* __restrict__ x, const float* __restrict__ dwg,
           const float* __restrict__ pwg, const float* __restrict__ s1g,
           const float* __restrict__ b1g, const float* __restrict__ s2g,
           const float* __restrict__ b2g, float* __restrict__ out) {
    extern __shared__ float sm[];
    float* Ys = sm;
    float* T1 = sm + TC_T1;
    float* Dw = sm + TC_DW;
    float* PR = sm + TC_PR;  // S1 | B1 | S2 | B2 (64 each)

    int tid = threadIdx.x;
    int t0 = blockIdx.x * TT2;
    int b = blockIdx.y;

    // ---- load Y tile with t-halo ----
    if (blockIdx.x > 0 && blockIdx.x < (int)gridDim.x - 1) {
        // interior: fully in-range, float4 fast path. per c: 300 contiguous floats.
        const float4* ysrc = (const float4*)(g_Y + ((size_t)b * NO * NT + (t0 - 4)) * NV);
        for (int i = tid; i < 4800; i += 256) {
            int c = i / 75, q = i - c * 75;
            ((float4*)Ys)[i] = ysrc[c * 3200 + q];
        }
    } else {
        for (int i = tid; i < NC * HT2 * NV; i += 256) {
            int c = i / (HT2 * NV);
            int q = i - c * (HT2 * NV);
            int tt = q / NV, v = q - tt * NV;
            int tg = t0 - 4 + tt;
            float val = 0.0f;
            if (tg >= 0 && tg < NT)
                val = g_Y[(((size_t)b * NO + c) * NT + tg) * NV + v];
            Ys[i] = val;
        }
    }
    for (int i = tid; i < NO * 9; i += 256) {
        int c = i / 9, j = i - c * 9;
        Dw[c * 12 + j] = dwg[i];
    }
    if (tid < 64) {
        PR[tid]       = s1g[tid];
        PR[64 + tid]  = b1g[tid];
        PR[128 + tid] = s2g[tid];
        PR[192 + tid] = b2g[tid];
    }
    __syncthreads();

    // ---- depthwise k=9 + BN1 + hswish -> T1 ----
    #pragma unroll 1
    for (int it = 0; it < 25; it++) {
        int i = tid + it * 256;
        int c = i / P2, p = i - c * P2;
        int tt = p / NV, v = p - tt * NV;
        const float* yr = Ys + c * (HT2 * NV) + tt * NV + v;
        const float* dr = Dw + c * 12;
        float a = 0.0f;
        #pragma unroll
        for (int j = 0; j < 9; j++) a = fmaf(yr[j * NV], dr[j], a);
        T1[i] = hswish(a * PR[c] + PR[64 + c]);
    }
    __syncthreads();

    // ---- pointwise 64x64 + BN2 + residual + hswish ----
    int og = tid >> 5, pt = tid & 31;
    bool hiok = (pt < 18);
    u64 acc[8][2];
    #pragma unroll
    for (int r = 0; r < 8; r++) { acc[r][0] = 0ull; acc[r][1] = 0ull; }

    for (int c4 = 0; c4 < 16; c4++) {
        u64 tv0[4], tv1[4];
        #pragma unroll
        for (int cc = 0; cc < 4; cc++) {
            const float* tp = T1 + (c4 * 4 + cc) * P2;
            tv0[cc] = *(const u64*)(tp + 2 * pt);
            tv1[cc] = hiok ? *(const u64*)(tp + 64 + 2 * pt) : 0ull;
        }
        #pragma unroll
        for (int r = 0; r < 8; r++) {
            float4 w4 = __ldg((const float4*)(pwg + (og * 8 + r) * 64 + c4 * 4));
            u64 w;
            w = dup2(w4.x); acc[r][0] = ffma2(w, tv0[0], acc[r][0]); acc[r][1] = ffma2(w, tv1[0], acc[r][1]);
            w = dup2(w4.y); acc[r][0] = ffma2(w, tv0[1], acc[r][0]); acc[r][1] = ffma2(w, tv1[1], acc[r][1]);
            w = dup2(w4.z); acc[r][0] = ffma2(w, tv0[2], acc[r][0]); acc[r][1] = ffma2(w, tv1[2], acc[r][1]);
            w = dup2(w4.w); acc[r][0] = ffma2(w, tv0[3], acc[r][0]); acc[r][1] = ffma2(w, tv1[3], acc[r][1]);
        }
    }

    #pragma unroll
    for (int r = 0; r < 8; r++) {
        int oo = og * 8 + r;
        float sc = PR[128 + oo], bb = PR[192 + oo];
        size_t base = (((size_t)b * NC + oo) * NT + t0) * NV;
        {
            float lo, hi; unpk(acc[r][0], lo, hi);
            float2 xa = *(const float2*)(x + base + 2 * pt);
            float2 res = make_float2(hswish(lo * sc + bb + xa.x),
                                     hswish(hi * sc + bb + xa.y));
            *(float2*)(out + base + 2 * pt) = res;
        }
        if (hiok) {
            float lo, hi; unpk(acc[r][1], lo, hi);
            float2 xa = *(const float2*)(x + base + 64 + 2 * pt);
            float2 res = make_float2(hswish(lo * sc + bb + xa.x),
                                     hswish(hi * sc + bb + xa.y));
            *(float2*)(out + base + 64 + 2 * pt) = res;
        }
    }
}

// ===================== launcher =====================
extern "C" void kernel_launch(void* const* d_in, const int* in_sizes, int n_in,
                              void* d_out, int out_size) {
    const float* x  = (const float*)d_in[0];
    const float* Af = (const float*)d_in[1];
    const float* Al = (const float*)d_in[2];
    const float* Wg = (const float*)d_in[3];
    const float* gs = (const float*)d_in[4];
    const float* gb = (const float*)d_in[5];
    const float* dw = (const float*)d_in[6];
    const float* pw = (const float*)d_in[7];
    const float* s1 = (const float*)d_in[8];
    const float* b1 = (const float*)d_in[9];
    const float* s2 = (const float*)d_in[10];
    const float* b2 = (const float*)d_in[11];
    float* out = (float*)d_out;

    (void)in_sizes; (void)n_in; (void)out_size;

    cudaFuncSetAttribute(gcn_kernel, cudaFuncAttributeMaxDynamicSharedMemorySize,
                         GC_TOT * (int)sizeof(float));
    cudaFuncSetAttribute(tcn_kernel, cudaFuncAttributeMaxDynamicSharedMemorySize,
                         TC_TOT * (int)sizeof(float));

    gcn_kernel<<<dim3(NT / TT, NB), 256, GC_TOT * sizeof(float)>>>(x, Af, Al, Wg, gs, gb);
    tcn_kernel<<<dim3(NT / TT2, NB), 256, TC_TOT * sizeof(float)>>>(x, dw, pw, s1, b1, s2, b2, out);
}

// round 15
// speedup vs baseline: 1.7655x; 1.1916x over previous
#include <cuda_runtime.h>
#include <math.h>

typedef unsigned long long u64;

#define NB 64
#define NC 64
#define NT 512
#define NV 25
#define NK 3
#define NO 64

// -------- scratch (device globals) --------
__device__ float g_Y[(size_t)NB * NO * NT * NV];   // GCN output after BN+hswish

__device__ __forceinline__ float hswish(float x) {
    return x * fminf(fmaxf(x + 3.0f, 0.0f), 6.0f) * (1.0f / 6.0f);
}
__device__ __forceinline__ u64 ffma2(u64 a, u64 b, u64 c) {
    u64 d; asm("fma.rn.f32x2 %0, %1, %2, %3;" : "=l"(d) : "l"(a), "l"(b), "l"(c)); return d;
}
__device__ __forceinline__ u64 dup2(float v) {
    u64 d; asm("mov.b64 %0, {%1, %1};" : "=l"(d) : "f"(v)); return d;
}
__device__ __forceinline__ void unpk(u64 p, float& lo, float& hi) {
    asm("mov.b64 {%0, %1}, %2;" : "=f"(lo), "=f"(hi) : "l"(p));
}

// ===================== K1: GCN (unchanged from R14) =====================
// grid (T/TT, B), 256 thr, 2 blocks/SM. k loop outermost: Uk[64][100] per k,
// stage-B accumulators persist in registers across k.
#define TT 4
#define P1 100
#define GC_UK 6400
#define GC_WS 12800
#define GC_AN 25088
#define GC_DSH 27488
#define GC_TOT 27568

__global__ void __launch_bounds__(256, 2)
gcn_kernel(const float* __restrict__ x,
           const float* __restrict__ Af, const float* __restrict__ Al,
           const float* __restrict__ Wg,
           const float* __restrict__ gscale, const float* __restrict__ gbias) {
    extern __shared__ float sm[];
    float* Xs = sm;
    float* Uk = sm + GC_UK;
    float* Ws = sm + GC_WS;
    float* An = sm + GC_AN;
    float* dsh = sm + GC_DSH;

    int tid = threadIdx.x;
    int t0 = blockIdx.x * TT;
    int b = blockIdx.y;

    // ---- D^{-1/2} row factors ----
    if (tid < NK * NV) {
        const float* af = Af + tid * NV;
        const float* al = Al + tid * NV;
        float s = 0.0f;
        #pragma unroll
        for (int w = 0; w < NV; w++) s += fabsf(af[w] + al[w]);
        dsh[tid] = rsqrtf(fmaxf(s, 1e-6f));
    }
    // ---- cooperative loads (all float4) ----
    {
        const float4* xsrc = (const float4*)(x + ((size_t)b * NC * NT + t0) * NV);
        for (int i = tid; i < 1600; i += 256) {
            int c = i / 25, q = i - c * 25;
            ((float4*)Xs)[i] = xsrc[c * 3200 + q];
        }
        const float4* wsrc = (const float4*)Wg;
        for (int i = tid; i < 3072; i += 256) ((float4*)Ws)[i] = wsrc[i];
    }
    __syncthreads();
    // ---- An fill ----
    for (int i = tid; i < NK * NV * 32; i += 256) {
        int row = i >> 5;          // k*25+v
        int w = i & 31;
        float val = 0.0f;
        if (w < NV) {
            int k = row / NV;
            int src = row * NV + w;
            val = dsh[row] * fabsf(Af[src] + Al[src]) * dsh[k * NV + w];
        }
        An[i] = val;
    }
    __syncthreads();

    int jg = tid >> 5, pt = tid & 31;
    bool hiok = (pt < 18);
    int o = tid >> 2, ttl = tid & 3;

    u64 bacc[14];
    #pragma unroll
    for (int j = 0; j < 14; j++) bacc[j] = 0ull;

    for (int k = 0; k < NK; k++) {
        // ---- stage A ----
        u64 acc[8][2];
        #pragma unroll
        for (int r = 0; r < 8; r++) { acc[r][0] = 0ull; acc[r][1] = 0ull; }
        const float* Wr = Ws + (k * 64 + jg * 8) * 64;
        for (int c4 = 0; c4 < 16; c4++) {
            u64 xv0[4], xv1[4];
            #pragma unroll
            for (int cc = 0; cc < 4; cc++) {
                const float* xp = Xs + (c4 * 4 + cc) * P1;
                xv0[cc] = *(const u64*)(xp + 2 * pt);
                xv1[cc] = hiok ? *(const u64*)(xp + 64 + 2 * pt) : 0ull;
            }
            #pragma unroll
            for (int r = 0; r < 8; r++) {
                float4 w4 = *(const float4*)(Wr + r * 64 + c4 * 4);
                u64 w;
                w = dup2(w4.x); acc[r][0] = ffma2(w, xv0[0], acc[r][0]); acc[r][1] = ffma2(w, xv1[0], acc[r][1]);
                w = dup2(w4.y); acc[r][0] = ffma2(w, xv0[1], acc[r][0]); acc[r][1] = ffma2(w, xv1[1], acc[r][1]);
                w = dup2(w4.z); acc[r][0] = ffma2(w, xv0[2], acc[r][0]); acc[r][1] = ffma2(w, xv1[2], acc[r][1]);
                w = dup2(w4.w); acc[r][0] = ffma2(w, xv0[3], acc[r][0]); acc[r][1] = ffma2(w, xv1[3], acc[r][1]);
            }
        }
        #pragma unroll
        for (int r = 0; r < 8; r++) {
            float* up = Uk + (jg * 8 + r) * P1;
            *(u64*)(up + 2 * pt) = acc[r][0];
            if (hiok) *(u64*)(up + 64 + 2 * pt) = acc[r][1];
        }
        __syncthreads();

        // ---- stage B ----
        {
            const float* Ur = Uk + o * P1 + ttl * NV;
            const float* Ar = An + k * (NV * 32);
            #pragma unroll 5
            for (int v = 0; v < NV; v++) {
                u64 uv = dup2(Ur[v]);
                const ulonglong2* A2 = (const ulonglong2*)(Ar + v * 32);
                #pragma unroll
                for (int q = 0; q < 7; q++) {
                    ulonglong2 aa = A2[q];
                    bacc[2 * q]     = ffma2(uv, aa.x, bacc[2 * q]);
                    bacc[2 * q + 1] = ffma2(uv, aa.y, bacc[2 * q + 1]);
                }
            }
        }
        __syncthreads();
    }

    // ---- epilogue ----
    {
        float s = gscale[o] * (1.0f / 3.0f);
        float bi = gbias[o];
        float* yrow = Xs + o * P1 + ttl * NV;
        #pragma unroll
        for (int j = 0; j < 13; j++) {
            float lo, hi; unpk(bacc[j], lo, hi);
            yrow[2 * j] = hswish(lo * s + bi);
            if (2 * j + 1 < NV) yrow[2 * j + 1] = hswish(hi * s + bi);
        }
    }
    __syncthreads();
    {
        float4* ydst = (float4*)(g_Y + ((size_t)b * NO * NT + t0) * NV);
        for (int i = tid; i < 1600; i += 256) {
            int oo = i / 25, q = i - oo * 25;
            ydst[oo * 3200 + q] = ((const float4*)Xs)[i];
        }
    }
}

// ===================== K2: TCN v2 =====================
// grid (T/4, B), 256 thr, 3 blocks/SM (46.1 KB smem).
// Depthwise: sliding-window per (c,v) column, 12 global taps -> 4 outputs.
// Pointwise: weights from smem (broadcast LDS.128), f32x2 accumulation.
// smem floats: T1[64][100] @0 6400, Pws[64][64] @6400 4096,
//              Dw[64][12] @10496 768, PR[256] @11264 -> 11520 fl = 46,080 B
#define TT2 4
#define P2 100
#define TC_PWS 6400
#define TC_DW 10496
#define TC_PR 11264
#define TC_TOT 11520

__global__ void __launch_bounds__(256, 3)
tcn_kernel(const float* __restrict__ x, const float* __restrict__ dwg,
           const float* __restrict__ pwg, const float* __restrict__ s1g,
           const float* __restrict__ b1g, const float* __restrict__ s2g,
           const float* __restrict__ b2g, float* __restrict__ out) {
    extern __shared__ float sm[];
    float* T1 = sm;
    float* Pws = sm + TC_PWS;
    float* Dw = sm + TC_DW;
    float* PR = sm + TC_PR;  // S1 | B1 | S2 | B2

    int tid = threadIdx.x;
    int t0 = blockIdx.x * TT2;
    int b = blockIdx.y;

    // ---- param loads ----
    {
        const float4* psrc = (const float4*)pwg;
        for (int i = tid; i < 1024; i += 256) ((float4*)Pws)[i] = psrc[i];
    }
    for (int i = tid; i < NO * 9; i += 256) {
        int c = i / 9, j = i - c * 9;
        Dw[c * 12 + j] = dwg[i];
    }
    if (tid < 64) {
        PR[tid]       = s1g[tid];
        PR[64 + tid]  = b1g[tid];
        PR[128 + tid] = s2g[tid];
        PR[192 + tid] = b2g[tid];
    }
    __syncthreads();

    // ---- depthwise k=9 + BN1 + hswish -> T1 (sliding window, direct g_Y reads) ----
    bool interior = (blockIdx.x > 0) && (blockIdx.x < (int)gridDim.x - 1);
    #pragma unroll 1
    for (int it = 0; it < 7; it++) {
        int i = tid + it * 256;
        if (i < 1600) {
            int c = i / 25, v = i - c * 25;
            const float* dr = Dw + c * 12;
            const float* ybase = g_Y + (((size_t)b * NO + c) * NT + t0 - 4) * NV + v;
            float w[12];
            if (interior) {
                #pragma unroll
                for (int j = 0; j < 12; j++) w[j] = __ldg(ybase + j * NV);
            } else {
                #pragma unroll
                for (int j = 0; j < 12; j++) {
                    int tg = t0 - 4 + j;
                    w[j] = (tg >= 0 && tg < NT) ? __ldg(ybase + j * NV) : 0.0f;
                }
            }
            float sc1 = PR[c], bb1 = PR[64 + c];
            #pragma unroll
            for (int tt = 0; tt < TT2; tt++) {
                float a = 0.0f;
                #pragma unroll
                for (int j = 0; j < 9; j++) a = fmaf(w[tt + j], dr[j], a);
                T1[c * P2 + tt * NV + v] = hswish(a * sc1 + bb1);
            }
        }
    }
    __syncthreads();

    // ---- pointwise 64x64 + BN2 + residual + hswish ----
    int og = tid >> 5, pt = tid & 31;
    bool hiok = (pt < 18);
    u64 acc[8][2];
    #pragma unroll
    for (int r = 0; r < 8; r++) { acc[r][0] = 0ull; acc[r][1] = 0ull; }

    for (int c4 = 0; c4 < 16; c4++) {
        u64 tv0[4], tv1[4];
        #pragma unroll
        for (int cc = 0; cc < 4; cc++) {
            const float* tp = T1 + (c4 * 4 + cc) * P2;
            tv0[cc] = *(const u64*)(tp + 2 * pt);
            tv1[cc] = hiok ? *(const u64*)(tp + 64 + 2 * pt) : 0ull;
        }
        #pragma unroll
        for (int r = 0; r < 8; r++) {
            float4 w4 = *(const float4*)(Pws + (og * 8 + r) * 64 + c4 * 4);
            u64 w;
            w = dup2(w4.x); acc[r][0] = ffma2(w, tv0[0], acc[r][0]); acc[r][1] = ffma2(w, tv1[0], acc[r][1]);
            w = dup2(w4.y); acc[r][0] = ffma2(w, tv0[1], acc[r][0]); acc[r][1] = ffma2(w, tv1[1], acc[r][1]);
            w = dup2(w4.z); acc[r][0] = ffma2(w, tv0[2], acc[r][0]); acc[r][1] = ffma2(w, tv1[2], acc[r][1]);
            w = dup2(w4.w); acc[r][0] = ffma2(w, tv0[3], acc[r][0]); acc[r][1] = ffma2(w, tv1[3], acc[r][1]);
        }
    }

    #pragma unroll
    for (int r = 0; r < 8; r++) {
        int oo = og * 8 + r;
        float sc = PR[128 + oo], bb = PR[192 + oo];
        size_t base = (((size_t)b * NC + oo) * NT + t0) * NV;
        {
            float lo, hi; unpk(acc[r][0], lo, hi);
            float2 xa = *(const float2*)(x + base + 2 * pt);
            float2 res = make_float2(hswish(lo * sc + bb + xa.x),
                                     hswish(hi * sc + bb + xa.y));
            *(float2*)(out + base + 2 * pt) = res;
        }
        if (hiok) {
            float lo, hi; unpk(acc[r][1], lo, hi);
            float2 xa = *(const float2*)(x + base + 64 + 2 * pt);
            float2 res = make_float2(hswish(lo * sc + bb + xa.x),
                                     hswish(hi * sc + bb + xa.y));
            *(float2*)(out + base + 64 + 2 * pt) = res;
        }
    }
}

// ===================== launcher =====================
extern "C" void kernel_launch(void* const* d_in, const int* in_sizes, int n_in,
                              void* d_out, int out_size) {
    const float* x  = (const float*)d_in[0];
    const float* Af = (const float*)d_in[1];
    const float* Al = (const float*)d_in[2];
    const float* Wg = (const float*)d_in[3];
    const float* gs = (const float*)d_in[4];
    const float* gb = (const float*)d_in[5];
    const float* dw = (const float*)d_in[6];
    const float* pw = (const float*)d_in[7];
    const float* s1 = (const float*)d_in[8];
    const float* b1 = (const float*)d_in[9];
    const float* s2 = (const float*)d_in[10];
    const float* b2 = (const float*)d_in[11];
    float* out = (float*)d_out;

    (void)in_sizes; (void)n_in; (void)out_size;

    cudaFuncSetAttribute(gcn_kernel, cudaFuncAttributeMaxDynamicSharedMemorySize,
                         GC_TOT * (int)sizeof(float));
    cudaFuncSetAttribute(tcn_kernel, cudaFuncAttributeMaxDynamicSharedMemorySize,
                         TC_TOT * (int)sizeof(float));

    gcn_kernel<<<dim3(NT / TT, NB), 256, GC_TOT * sizeof(float)>>>(x, Af, Al, Wg, gs, gb);
    tcn_kernel<<<dim3(NT / TT2, NB), 256, TC_TOT * sizeof(float)>>>(x, dw, pw, s1, b1, s2, b2, out);
}